// round 10
// baseline (speedup 1.0000x reference)
#include <cuda_runtime.h>
#include <cuda_fp16.h>
#include <math.h>

#define BB 16
#define HH 56
#define WW 56
#define CC 128
#define HW 3136
#define NELEM (BB*HW*CC)   // 6422528
#define CH 4               // channels per block in main kernel
#define CST 3300           // padded per-channel SAT stride (floats); 3300 % 32 == 4
#define NSUB 56            // minmax partials per batch

// ---------------- device scratch (no allocation allowed) ----------------
__device__ uint4  g_t12h[NELEM/4];    // packed half2(t1,t2) per element, 16B-aligned
__device__ float  g_squeeze[BB*CC];
__device__ float  g_pmin[BB*NSUB];
__device__ float  g_pmax[BB*NSUB];
__device__ float  g_bv[5];
__device__ float  g_nbv;

// ---------------- kernel A: per-batch partial min/max + scale constants ----------------
// 896 blocks = 16 batches x 56 subs; each thread: 7 fully-unrolled independent float4 loads
__global__ void __launch_bounds__(256) k_minmax(const float* __restrict__ x,
                                                const float* __restrict__ kappa){
    int b = blockIdx.x / NSUB, sub = blockIdx.x % NSUB;
    const float4* xb = (const float4*)(x + (size_t)b*HW*CC);
    int base = sub*1792 + threadIdx.x;          // 1792 float4 per sub-block
    float mn0=3.4e38f, mn1=3.4e38f, mn2=3.4e38f, mn3=3.4e38f;
    float mx0=-3.4e38f, mx1=-3.4e38f, mx2=-3.4e38f, mx3=-3.4e38f;
    #pragma unroll
    for (int k = 0; k < 7; k++){
        float4 v = xb[base + k*256];
        mn0 = fminf(mn0, v.x); mx0 = fmaxf(mx0, v.x);
        mn1 = fminf(mn1, v.y); mx1 = fmaxf(mx1, v.y);
        mn2 = fminf(mn2, v.z); mx2 = fmaxf(mx2, v.z);
        mn3 = fminf(mn3, v.w); mx3 = fmaxf(mx3, v.w);
    }
    float mn = fminf(fminf(mn0,mn1), fminf(mn2,mn3));
    float mx = fmaxf(fmaxf(mx0,mx1), fmaxf(mx2,mx3));
    #pragma unroll
    for (int o = 16; o; o >>= 1){
        mn = fminf(mn, __shfl_xor_sync(~0u, mn, o));
        mx = fmaxf(mx, __shfl_xor_sync(~0u, mx, o));
    }
    __shared__ float smn[8], smx[8];
    int lane = threadIdx.x & 31, wp = threadIdx.x >> 5;
    if (lane == 0){ smn[wp] = mn; smx[wp] = mx; }
    __syncthreads();
    if (threadIdx.x == 0){
        for (int i = 1; i < 8; i++){ mn = fminf(mn, smn[i]); mx = fmaxf(mx, smx[i]); }
        g_pmin[b*NSUB+sub] = mn;
        g_pmax[b*NSUB+sub] = mx;
    }
    if (blockIdx.x == 0 && threadIdx.x == 32){
        const float LN2 = 0.6931471805599453f;
        float v[5]; float mean = 0.f;
        for (int s = 0; s < 5; s++){
            float kk   = 1.f/(1.f + expf(-kappa[s]));
            float lk   = logf(kk + 1e-7f);
            float logk = 1.f/(1.f + expf(-lk));
            v[s] = logk + (float)(s+1)*LN2;        // log_k + log_r
            mean += v[s];
        }
        mean *= 0.2f;
        float bv[5]; float bsum = 0.f;
        for (int s = 0; s < 5; s++){ bv[s] = v[s]-mean; bsum += bv[s]; }
        bsum *= 0.2f;                               // force sum(bv) == 0 exactly
        float n2 = 0.f;
        for (int s = 0; s < 5; s++){ bv[s] -= bsum; g_bv[s] = bv[s]; n2 += bv[s]*bv[s]; }
        g_nbv = sqrtf(n2);
    }
}

// ---------------- kernel B: SAT + alphas + sim, emit packed t12 + squeeze ----------------
__global__ void __launch_bounds__(256) k_main(
    const float* __restrict__ x,
    const float* __restrict__ gamma, const float* __restrict__ beta,
    const float* __restrict__ bn_mean, const float* __restrict__ bn_var)
{
    extern __shared__ float sat[];      // CH * CST floats (52.8 KB)
    int b  = blockIdx.y;
    int c0 = blockIdx.x * CH;
    int t  = threadIdx.x;               // 256
    int ci = t & 3;
    int c  = c0 + ci;

    // reduce the 56 partial min/max for this batch (warp 0)
    __shared__ float s_mm[2];
    if (t < 32){
        float mnv = g_pmin[b*NSUB + t];
        float mxv = g_pmax[b*NSUB + t];
        if (t < 24){
            mnv = fminf(mnv, g_pmin[b*NSUB + 32 + t]);
            mxv = fmaxf(mxv, g_pmax[b*NSUB + 32 + t]);
        }
        #pragma unroll
        for (int o = 16; o; o >>= 1){
            mnv = fminf(mnv, __shfl_xor_sync(~0u, mnv, o));
            mxv = fmaxf(mxv, __shfl_xor_sync(~0u, mxv, o));
        }
        if (t == 0){ s_mm[0] = mnv; s_mm[1] = mxv; }
    }
    // zero SAT borders (row 0, col 0 of each 57x57 table); CH*57 = 228 < 256
    if (t < CH*57){
        int cc = t/57, j = t%57;
        sat[cc*CST + j]      = 0.f;     // row 0
        sat[cc*CST + j*57]   = 0.f;     // col 0
    }
    __syncthreads();
    float xmin = s_mm[0];
    float xmax = s_mm[1];
    float inv  = 1.f/(xmax - xmin + 1e-7f);
    const float* xb = x + (size_t)b*HW*CC;

    // load normalized xs into SAT interior (4 consecutive channels per pixel)
    #pragma unroll 4
    for (int idx = t; idx < HW*CH; idx += 256){
        int cc = idx & 3; int p = idx >> 2;
        int h = p/56, w = p - h*56;
        float v = (xb[p*CC + c0 + cc] - xmin) * inv;
        sat[cc*CST + (h+1)*57 + (w+1)] = v;
    }
    __syncthreads();

    // row prefix sums (224 rows, one per thread)
    if (t < CH*56){
        int cc = t/56; int i = (t%56) + 1;
        float* row = sat + cc*CST + i*57;
        float acc = 0.f;
        #pragma unroll
        for (int j = 1; j <= 56; j++){ acc += row[j]; row[j] = acc; }
    }
    __syncthreads();

    // column prefix sums (224 cols, one per thread)
    if (t < CH*56){
        int cc = t/56; int j = (t%56) + 1;
        float* col = sat + cc*CST + j;
        float acc = 0.f;
        #pragma unroll
        for (int i = 1; i <= 56; i++){ acc += col[i*57]; col[i*57] = acc; }
    }
    __syncthreads();

    // per-thread constants
    float bns = gamma[c] * rsqrtf(bn_var[c] + 1e-3f);
    float bnb = beta[c] - bns*bn_mean[c];
    float bv0 = g_bv[0], bv1 = g_bv[1], bv2 = g_bv[2], bv3 = g_bv[3], bv4 = g_bv[4];
    const float LN2 = 0.69314718055994531f;
    float C1  = LN2 * g_nbv;            // multiplies sqrt(na2)*|alpha|
    const float* S = sat + ci*CST;
    __half2* t12p = ((__half2*)g_t12h) + (size_t)b*HW*CC;

    float asum = 0.f;
    int p0 = t >> 2;                   // 0..63, pixel stride 64 per iter
    const int KK[5] = {2,4,8,16,32};
    const int PB[5] = {0,1,3,7,15};    // TF SAME pad_before = (k-1)/2

    int h = p0/56, w = p0 - 56*(p0/56);
    float xcur = __ldg(&xb[p0*CC + c]);            // prefetched x for iter 0

    for (int it = 0; it < 49; it++){
        int p = p0 + it*64;
        // prefetch next iteration's x (L2 hit) before the math
        float xnext = 0.f;
        if (it < 48) xnext = __ldg(&xb[(p+64)*CC + c]);

        float L[5];   // log2(m + eps)  -- MUFU LG2, everything stays in log2 basis
        #pragma unroll
        for (int s = 0; s < 5; s++){
            int r0 = max(h - PB[s], 0), r1 = min(h - PB[s] + KK[s], 56);
            int q0 = max(w - PB[s], 0), q1 = min(w - PB[s] + KK[s], 56);
            float m = S[r1*57 + q1] - S[r0*57 + q1] - S[r1*57 + q0] + S[r0*57 + q0];
            L[s] = __log2f(m + 1e-7f);
        }
        float sumL = (L[0]+L[1]) + (L[2]+L[3]) + L[4];
        // alpha (natural-log OLS slope) == 0.1*(2(L4-L0)+(L3-L1)) in log2 basis
        float alpha = 0.1f * (2.f*(L[4]-L[0]) + (L[3]-L[1]));
        // dot(a,bv) = sum(L*bv) since sum(bv)==0 ;  |a|^2 = sum(L^2) - (sum L)^2/5
        float dotv = L[0]*bv0 + L[1]*bv1 + L[2]*bv2 + L[3]*bv3 + L[4]*bv4;
        float sq   = L[0]*L[0] + L[1]*L[1] + L[2]*L[2] + L[3]*L[3] + L[4]*L[4];
        float na2  = fmaxf(fmaf(-0.2f*sumL, sumL, sq), 0.f);
        float rs   = rsqrtf(na2 + 1e-20f);
        float sqn  = na2 * rs;                              // sqrt(na2), ==0 when na2==0
        float D    = fmaf(sqn * fabsf(alpha), C1, 1e-7f);
        float N    = LN2 * alpha * dotv;
        float u    = 0.5f * N * __fdividef(1.f, D);         // 0.5*cos
        float sim  = 0.5f + u;
        float oms  = 0.5f - u;                              // 1 - sim
        float sg   = __fdividef(1.f, 1.f + __expf(-fmaf(bns, alpha, bnb)));
        float xs   = (xcur - xmin) * inv;
        t12p[p*CC + c] = __floats2half2_rn(sim * sg, oms * xs);
        asum += alpha;
        xcur = xnext;
        // advance pixel by 64 = 56 + 8
        h += 1; w += 8;
        if (w >= 56){ w -= 56; h += 1; }
    }

    // per-channel alpha sum -> squeeze (block owns full H*W of its 4 channels)
    // lane = (pixel-group bits 2..4) | ci(bits 0..1): reduce over pixel bits
    asum += __shfl_xor_sync(~0u, asum, 4);
    asum += __shfl_xor_sync(~0u, asum, 8);
    asum += __shfl_xor_sync(~0u, asum, 16);
    __shared__ float red[8][4];
    int lane = t & 31, wp = t >> 5;
    if (lane < 4) red[wp][lane] = asum;
    __syncthreads();
    if (t < 4){
        float s = 0.f;
        #pragma unroll
        for (int i = 0; i < 8; i++) s += red[i][t];
        g_squeeze[b*CC + c0 + t] = s * (1.f/3136.f);
    }
}

// ---------------- kernel C: per-block SE-MLP (smem) + final blend ----------------
__global__ void __launch_bounds__(256) k_final(
    float* __restrict__ out,
    const float* __restrict__ W1, const float* __restrict__ b1,
    const float* __restrict__ W2, const float* __restrict__ b2)
{
    // each block covers 1024 out-float4 = 4096 floats; batch slab = 98 blocks
    int blk = blockIdx.x;
    int b   = blk / 98;
    int t   = threadIdx.x;

    __shared__ float s_sq[CC];
    __shared__ float s_hid[16];
    __shared__ float s_exc[CC];

    if (t < CC) s_sq[t] = g_squeeze[b*CC + t];
    __syncthreads();

    // hidden[j] = relu(b1[j] + sum_c sq[c]*W1[c*16+j]); 256 thr = (j<16) x (cl<16)
    {
        int j = t >> 4, cl = t & 15;
        float acc = 0.f;
        #pragma unroll
        for (int k = 0; k < 8; k++){
            int cc = cl + 16*k;
            acc += s_sq[cc] * __ldg(&W1[cc*16 + j]);
        }
        #pragma unroll
        for (int o = 8; o; o >>= 1) acc += __shfl_xor_sync(~0u, acc, o);
        if (cl == 0) s_hid[j] = fmaxf(acc + __ldg(&b1[j]), 0.f);
    }
    __syncthreads();

    if (t < CC){
        float a = __ldg(&b2[t]);
        #pragma unroll
        for (int j = 0; j < 16; j++) a += s_hid[j] * __ldg(&W2[j*CC + t]);
        s_exc[t] = __fdividef(1.f, 1.f + __expf(-a));
    }
    __syncthreads();

    const float4* exc4 = (const float4*)s_exc;
    #pragma unroll
    for (int it = 0; it < 4; it++){
        int i = blk*1024 + it*256 + t;      // out float4 index (4 channels)
        uint4 u = g_t12h[i];                // 4 x half2(t1,t2)
        float2 p0 = __half22float2(*(__half2*)&u.x);
        float2 p1 = __half22float2(*(__half2*)&u.y);
        float2 p2 = __half22float2(*(__half2*)&u.z);
        float2 p3 = __half22float2(*(__half2*)&u.w);
        float4 e = exc4[i & 31];
        float4 o;
        o.x = fmaf(p0.y, e.x, p0.x);
        o.y = fmaf(p1.y, e.y, p1.x);
        o.z = fmaf(p2.y, e.z, p2.x);
        o.w = fmaf(p3.y, e.w, p3.x);
        ((float4*)out)[i] = o;
    }
}

// ---------------- launch ----------------
extern "C" void kernel_launch(void* const* d_in, const int* in_sizes, int n_in,
                              void* d_out, int out_size)
{
    const float* x       = (const float*)d_in[0];
    const float* kappa   = (const float*)d_in[1];
    const float* W1      = (const float*)d_in[2];
    const float* b1      = (const float*)d_in[3];
    const float* W2      = (const float*)d_in[4];
    const float* b2      = (const float*)d_in[5];
    const float* gamma   = (const float*)d_in[6];
    const float* beta    = (const float*)d_in[7];
    const float* bn_mean = (const float*)d_in[8];
    const float* bn_var  = (const float*)d_in[9];

    cudaFuncSetAttribute(k_main, cudaFuncAttributeMaxDynamicSharedMemorySize, CH*CST*4);

    k_minmax<<<BB*NSUB, 256>>>(x, kappa);
    dim3 gb(CC/CH, BB);
    k_main<<<gb, 256, CH*CST*4>>>(x, gamma, beta, bn_mean, bn_var);
    k_final<<<NELEM/4096, 256>>>((float*)d_out, W1, b1, W2, b2);
}

// round 11
// speedup vs baseline: 1.1660x; 1.1660x over previous
#include <cuda_runtime.h>
#include <cuda_fp16.h>
#include <math.h>

#define BB 16
#define HH 56
#define WW 56
#define CC 128
#define HW 3136
#define NELEM (BB*HW*CC)   // 6422528
#define CH 8               // channels per block in main kernel
#define CST 3300           // padded per-channel SAT stride (floats); 3300 % 32 == 4
#define NSUB 56            // minmax partials per batch

// ---------------- device scratch (no allocation allowed) ----------------
__device__ uint4  g_t12h[NELEM/4];    // packed half2(t1,t2) per element, 16B-aligned
__device__ float  g_squeeze[BB*CC];
__device__ float  g_pmin[BB*NSUB];
__device__ float  g_pmax[BB*NSUB];
__device__ float  g_bv[5];
__device__ float  g_nbv;

// ---------------- kernel A: per-batch partial min/max + scale constants ----------------
// 896 blocks = 16 batches x 56 subs; each thread: 7 fully-unrolled independent float4 loads
__global__ void __launch_bounds__(256) k_minmax(const float* __restrict__ x,
                                                const float* __restrict__ kappa){
    int b = blockIdx.x / NSUB, sub = blockIdx.x % NSUB;
    const float4* xb = (const float4*)(x + (size_t)b*HW*CC);
    int base = sub*1792 + threadIdx.x;          // 1792 float4 per sub-block
    float mn0=3.4e38f, mn1=3.4e38f, mn2=3.4e38f, mn3=3.4e38f;
    float mx0=-3.4e38f, mx1=-3.4e38f, mx2=-3.4e38f, mx3=-3.4e38f;
    #pragma unroll
    for (int k = 0; k < 7; k++){
        float4 v = xb[base + k*256];
        mn0 = fminf(mn0, v.x); mx0 = fmaxf(mx0, v.x);
        mn1 = fminf(mn1, v.y); mx1 = fmaxf(mx1, v.y);
        mn2 = fminf(mn2, v.z); mx2 = fmaxf(mx2, v.z);
        mn3 = fminf(mn3, v.w); mx3 = fmaxf(mx3, v.w);
    }
    float mn = fminf(fminf(mn0,mn1), fminf(mn2,mn3));
    float mx = fmaxf(fmaxf(mx0,mx1), fmaxf(mx2,mx3));
    #pragma unroll
    for (int o = 16; o; o >>= 1){
        mn = fminf(mn, __shfl_xor_sync(~0u, mn, o));
        mx = fmaxf(mx, __shfl_xor_sync(~0u, mx, o));
    }
    __shared__ float smn[8], smx[8];
    int lane = threadIdx.x & 31, wp = threadIdx.x >> 5;
    if (lane == 0){ smn[wp] = mn; smx[wp] = mx; }
    __syncthreads();
    if (threadIdx.x == 0){
        for (int i = 1; i < 8; i++){ mn = fminf(mn, smn[i]); mx = fmaxf(mx, smx[i]); }
        g_pmin[b*NSUB+sub] = mn;
        g_pmax[b*NSUB+sub] = mx;
    }
    if (blockIdx.x == 0 && threadIdx.x == 32){
        const float LN2 = 0.6931471805599453f;
        float v[5]; float mean = 0.f;
        for (int s = 0; s < 5; s++){
            float kk   = 1.f/(1.f + expf(-kappa[s]));
            float lk   = logf(kk + 1e-7f);
            float logk = 1.f/(1.f + expf(-lk));
            v[s] = logk + (float)(s+1)*LN2;        // log_k + log_r
            mean += v[s];
        }
        mean *= 0.2f;
        float bv[5]; float bsum = 0.f;
        for (int s = 0; s < 5; s++){ bv[s] = v[s]-mean; bsum += bv[s]; }
        bsum *= 0.2f;                               // force sum(bv) == 0 exactly
        float n2 = 0.f;
        for (int s = 0; s < 5; s++){ bv[s] -= bsum; g_bv[s] = bv[s]; n2 += bv[s]*bv[s]; }
        g_nbv = sqrtf(n2);
    }
}

// ---------------- kernel B: SAT + alphas + sim, emit packed t12 + squeeze ----------------
__global__ void __launch_bounds__(512) k_main(
    const float* __restrict__ x,
    const float* __restrict__ gamma, const float* __restrict__ beta,
    const float* __restrict__ bn_mean, const float* __restrict__ bn_var)
{
    extern __shared__ float sat[];      // CH * CST floats (105.6 KB)
    int b  = blockIdx.y;
    int c0 = blockIdx.x * CH;
    int t  = threadIdx.x;               // 512
    int ci = t & 7;
    int c  = c0 + ci;

    // reduce the 56 partial min/max for this batch (warp 0)
    __shared__ float s_mm[2];
    if (t < 32){
        float mnv = g_pmin[b*NSUB + t];
        float mxv = g_pmax[b*NSUB + t];
        if (t < 24){
            mnv = fminf(mnv, g_pmin[b*NSUB + 32 + t]);
            mxv = fmaxf(mxv, g_pmax[b*NSUB + 32 + t]);
        }
        #pragma unroll
        for (int o = 16; o; o >>= 1){
            mnv = fminf(mnv, __shfl_xor_sync(~0u, mnv, o));
            mxv = fmaxf(mxv, __shfl_xor_sync(~0u, mxv, o));
        }
        if (t == 0){ s_mm[0] = mnv; s_mm[1] = mxv; }
    }
    // zero SAT borders (row 0, col 0 of each 57x57 table); CH*57 = 456 < 512
    if (t < CH*57){
        int cc = t/57, j = t%57;
        sat[cc*CST + j]      = 0.f;     // row 0
        sat[cc*CST + j*57]   = 0.f;     // col 0
    }
    __syncthreads();
    float xmin = s_mm[0];
    float xmax = s_mm[1];
    float inv  = 1.f/(xmax - xmin + 1e-7f);
    const float* xb = x + (size_t)b*HW*CC;

    // load normalized xs into SAT interior (coalesced: 8 consecutive channels per pixel)
    for (int idx = t; idx < HW*CH; idx += 512){
        int cc = idx & 7; int p = idx >> 3;
        int h = p/56, w = p - h*56;
        float v = (xb[p*CC + c0 + cc] - xmin) * inv;
        sat[cc*CST + (h+1)*57 + (w+1)] = v;
    }
    __syncthreads();

    // row prefix sums (448 rows, one per thread)
    if (t < 448){
        int cc = t/56; int i = (t%56) + 1;
        float* row = sat + cc*CST + i*57;
        float acc = 0.f;
        #pragma unroll
        for (int j = 1; j <= 56; j++){ acc += row[j]; row[j] = acc; }
    }
    __syncthreads();

    // column prefix sums (448 cols, one per thread)
    if (t < 448){
        int cc = t/56; int j = (t%56) + 1;
        float* col = sat + cc*CST + j;
        float acc = 0.f;
        #pragma unroll
        for (int i = 1; i <= 56; i++){ acc += col[i*57]; col[i*57] = acc; }
    }
    __syncthreads();

    // per-thread constants
    float bns = gamma[c] * rsqrtf(bn_var[c] + 1e-3f);
    float bnb = beta[c] - bns*bn_mean[c];
    float bv0 = g_bv[0], bv1 = g_bv[1], bv2 = g_bv[2], bv3 = g_bv[3], bv4 = g_bv[4];
    const float LN2 = 0.69314718055994531f;
    float C1  = LN2 * g_nbv;            // multiplies sqrt(na2)*|alpha|
    const float* S = sat + ci*CST;
    __half2* t12p = ((__half2*)g_t12h) + (size_t)b*HW*CC;

    float asum = 0.f;
    int p0 = t >> 3;                   // 0..63, pixel stride 64 per iter
    const int KK[5] = {2,4,8,16,32};
    const int PB[5] = {0,1,3,7,15};    // TF SAME pad_before = (k-1)/2

    int h = p0/56, w = p0 - 56*(p0/56);
    float xcur = __ldg(&xb[p0*CC + c]);            // prefetched x for iter 0

    #pragma unroll 2
    for (int it = 0; it < 49; it++){
        int p = p0 + it*64;
        // prefetch next iteration's x (L2 hit) before the math
        float xnext = 0.f;
        if (it < 48) xnext = __ldg(&xb[(p+64)*CC + c]);

        float L[5];   // log2(m + eps)  -- MUFU LG2, everything stays in log2 basis
        #pragma unroll
        for (int s = 0; s < 5; s++){
            int r0 = max(h - PB[s], 0), r1 = min(h - PB[s] + KK[s], 56);
            int q0 = max(w - PB[s], 0), q1 = min(w - PB[s] + KK[s], 56);
            float m = S[r1*57 + q1] - S[r0*57 + q1] - S[r1*57 + q0] + S[r0*57 + q0];
            L[s] = __log2f(m + 1e-7f);
        }
        float sumL = (L[0]+L[1]) + (L[2]+L[3]) + L[4];
        // alpha (natural-log OLS slope) == 0.1*(2(L4-L0)+(L3-L1)) in log2 basis
        float alpha = 0.1f * (2.f*(L[4]-L[0]) + (L[3]-L[1]));
        // dot(a,bv) = sum(L*bv) since sum(bv)==0 ;  |a|^2 = sum(L^2) - (sum L)^2/5
        float dotv = L[0]*bv0 + L[1]*bv1 + L[2]*bv2 + L[3]*bv3 + L[4]*bv4;
        float sq   = L[0]*L[0] + L[1]*L[1] + L[2]*L[2] + L[3]*L[3] + L[4]*L[4];
        float na2  = fmaxf(fmaf(-0.2f*sumL, sumL, sq), 0.f);
        float rs   = rsqrtf(na2 + 1e-20f);
        float sqn  = na2 * rs;                              // sqrt(na2), ==0 when na2==0
        float D    = fmaf(sqn * fabsf(alpha), C1, 1e-7f);
        float N    = LN2 * alpha * dotv;
        float u    = 0.5f * N * __fdividef(1.f, D);         // 0.5*cos
        float sim  = 0.5f + u;
        float oms  = 0.5f - u;                              // 1 - sim
        float sg   = __fdividef(1.f, 1.f + __expf(-fmaf(bns, alpha, bnb)));
        float xs   = (xcur - xmin) * inv;
        t12p[p*CC + c] = __floats2half2_rn(sim * sg, oms * xs);
        asum += alpha;
        xcur = xnext;
        // advance pixel by 64 = 56 + 8
        h += 1; w += 8;
        if (w >= 56){ w -= 56; h += 1; }
    }

    // per-channel alpha sum -> squeeze (block owns full H*W of its 8 channels)
    asum += __shfl_xor_sync(~0u, asum, 8);
    asum += __shfl_xor_sync(~0u, asum, 16);
    __shared__ float red[16][8];
    int lane = t & 31, wp = t >> 5;
    if (lane < 8) red[wp][lane] = asum;
    __syncthreads();
    if (t < 8){
        float s = 0.f;
        #pragma unroll
        for (int i = 0; i < 16; i++) s += red[i][t];
        g_squeeze[b*CC + c0 + t] = s * (1.f/3136.f);
    }
}

// ---------------- kernel C: per-block SE-MLP (smem) + final blend ----------------
__global__ void __launch_bounds__(256) k_final(
    float* __restrict__ out,
    const float* __restrict__ W1, const float* __restrict__ b1,
    const float* __restrict__ W2, const float* __restrict__ b2)
{
    // each block covers 1024 out-float4 = 4096 floats; batch slab = 98 blocks
    int blk = blockIdx.x;
    int b   = blk / 98;
    int t   = threadIdx.x;

    __shared__ float s_sq[CC];
    __shared__ float s_hid[16];
    __shared__ float s_exc[CC];

    if (t < CC) s_sq[t] = g_squeeze[b*CC + t];
    __syncthreads();

    // hidden[j] = relu(b1[j] + sum_c sq[c]*W1[c*16+j]); 256 thr = (j<16) x (cl<16)
    {
        int j = t >> 4, cl = t & 15;
        float acc = 0.f;
        #pragma unroll
        for (int k = 0; k < 8; k++){
            int cc = cl + 16*k;
            acc += s_sq[cc] * __ldg(&W1[cc*16 + j]);
        }
        #pragma unroll
        for (int o = 8; o; o >>= 1) acc += __shfl_xor_sync(~0u, acc, o);
        if (cl == 0) s_hid[j] = fmaxf(acc + __ldg(&b1[j]), 0.f);
    }
    __syncthreads();

    if (t < CC){
        float a = __ldg(&b2[t]);
        #pragma unroll
        for (int j = 0; j < 16; j++) a += s_hid[j] * __ldg(&W2[j*CC + t]);
        s_exc[t] = __fdividef(1.f, 1.f + __expf(-a));
    }
    __syncthreads();

    const float4* exc4 = (const float4*)s_exc;
    #pragma unroll
    for (int it = 0; it < 4; it++){
        int i = blk*1024 + it*256 + t;      // out float4 index (4 channels)
        uint4 u = g_t12h[i];                // 4 x half2(t1,t2)
        float2 p0 = __half22float2(*(__half2*)&u.x);
        float2 p1 = __half22float2(*(__half2*)&u.y);
        float2 p2 = __half22float2(*(__half2*)&u.z);
        float2 p3 = __half22float2(*(__half2*)&u.w);
        float4 e = exc4[i & 31];
        float4 o;
        o.x = fmaf(p0.y, e.x, p0.x);
        o.y = fmaf(p1.y, e.y, p1.x);
        o.z = fmaf(p2.y, e.z, p2.x);
        o.w = fmaf(p3.y, e.w, p3.x);
        ((float4*)out)[i] = o;
    }
}

// ---------------- launch ----------------
extern "C" void kernel_launch(void* const* d_in, const int* in_sizes, int n_in,
                              void* d_out, int out_size)
{
    const float* x       = (const float*)d_in[0];
    const float* kappa   = (const float*)d_in[1];
    const float* W1      = (const float*)d_in[2];
    const float* b1      = (const float*)d_in[3];
    const float* W2      = (const float*)d_in[4];
    const float* b2      = (const float*)d_in[5];
    const float* gamma   = (const float*)d_in[6];
    const float* beta    = (const float*)d_in[7];
    const float* bn_mean = (const float*)d_in[8];
    const float* bn_var  = (const float*)d_in[9];

    cudaFuncSetAttribute(k_main, cudaFuncAttributeMaxDynamicSharedMemorySize, CH*CST*4);

    k_minmax<<<BB*NSUB, 256>>>(x, kappa);
    dim3 gb(CC/CH, BB);
    k_main<<<gb, 512, CH*CST*4>>>(x, gamma, beta, bn_mean, bn_var);
    k_final<<<NELEM/4096, 256>>>((float*)d_out, W1, b1, W2, b2);
}

// round 12
// speedup vs baseline: 1.1991x; 1.0284x over previous
#include <cuda_runtime.h>
#include <cuda_fp16.h>
#include <math.h>

#define BB 16
#define HH 56
#define WW 56
#define CC 128
#define HW 3136
#define NELEM (BB*HW*CC)   // 6422528
#define CH 8               // channels per block in main kernel
#define CST 3300           // padded per-channel SAT stride (floats); 3300 % 32 == 4
#define NSUB 56            // minmax partials per batch
#define TMB 768            // k_main threads per block
#define NPG (TMB/CH)       // 96 pixel groups per block

// ---------------- device scratch (no allocation allowed) ----------------
__device__ uint4  g_t12h[NELEM/4];    // packed half2(t1,t2) per element, 16B-aligned
__device__ float  g_squeeze[BB*CC];
__device__ float  g_pmin[BB*NSUB];
__device__ float  g_pmax[BB*NSUB];
__device__ float  g_bv[5];
__device__ float  g_nbv;

// ---------------- kernel A: per-batch partial min/max + scale constants ----------------
// 896 blocks = 16 batches x 56 subs; each thread: 7 fully-unrolled independent float4 loads
__global__ void __launch_bounds__(256) k_minmax(const float* __restrict__ x,
                                                const float* __restrict__ kappa){
    int b = blockIdx.x / NSUB, sub = blockIdx.x % NSUB;
    const float4* xb = (const float4*)(x + (size_t)b*HW*CC);
    int base = sub*1792 + threadIdx.x;          // 1792 float4 per sub-block
    float mn0=3.4e38f, mn1=3.4e38f, mn2=3.4e38f, mn3=3.4e38f;
    float mx0=-3.4e38f, mx1=-3.4e38f, mx2=-3.4e38f, mx3=-3.4e38f;
    #pragma unroll
    for (int k = 0; k < 7; k++){
        float4 v = xb[base + k*256];
        mn0 = fminf(mn0, v.x); mx0 = fmaxf(mx0, v.x);
        mn1 = fminf(mn1, v.y); mx1 = fmaxf(mx1, v.y);
        mn2 = fminf(mn2, v.z); mx2 = fmaxf(mx2, v.z);
        mn3 = fminf(mn3, v.w); mx3 = fmaxf(mx3, v.w);
    }
    float mn = fminf(fminf(mn0,mn1), fminf(mn2,mn3));
    float mx = fmaxf(fmaxf(mx0,mx1), fmaxf(mx2,mx3));
    #pragma unroll
    for (int o = 16; o; o >>= 1){
        mn = fminf(mn, __shfl_xor_sync(~0u, mn, o));
        mx = fmaxf(mx, __shfl_xor_sync(~0u, mx, o));
    }
    __shared__ float smn[8], smx[8];
    int lane = threadIdx.x & 31, wp = threadIdx.x >> 5;
    if (lane == 0){ smn[wp] = mn; smx[wp] = mx; }
    __syncthreads();
    if (threadIdx.x == 0){
        for (int i = 1; i < 8; i++){ mn = fminf(mn, smn[i]); mx = fmaxf(mx, smx[i]); }
        g_pmin[b*NSUB+sub] = mn;
        g_pmax[b*NSUB+sub] = mx;
    }
    if (blockIdx.x == 0 && threadIdx.x == 32){
        const float LN2 = 0.6931471805599453f;
        float v[5]; float mean = 0.f;
        for (int s = 0; s < 5; s++){
            float kk   = 1.f/(1.f + expf(-kappa[s]));
            float lk   = logf(kk + 1e-7f);
            float logk = 1.f/(1.f + expf(-lk));
            v[s] = logk + (float)(s+1)*LN2;        // log_k + log_r
            mean += v[s];
        }
        mean *= 0.2f;
        float bv[5]; float bsum = 0.f;
        for (int s = 0; s < 5; s++){ bv[s] = v[s]-mean; bsum += bv[s]; }
        bsum *= 0.2f;                               // force sum(bv) == 0 exactly
        float n2 = 0.f;
        for (int s = 0; s < 5; s++){ bv[s] -= bsum; g_bv[s] = bv[s]; n2 += bv[s]*bv[s]; }
        g_nbv = sqrtf(n2);
    }
}

// ---------------- kernel B: SAT + alphas + sim, emit packed t12 + squeeze ----------------
__global__ void __launch_bounds__(TMB, 2) k_main(
    const float* __restrict__ x,
    const float* __restrict__ gamma, const float* __restrict__ beta,
    const float* __restrict__ bn_mean, const float* __restrict__ bn_var)
{
    extern __shared__ float sat[];      // CH * CST floats (105.6 KB)
    int b  = blockIdx.y;
    int c0 = blockIdx.x * CH;
    int t  = threadIdx.x;               // 768
    int ci = t & 7;
    int c  = c0 + ci;

    // reduce the 56 partial min/max for this batch (warp 0)
    __shared__ float s_mm[2];
    if (t < 32){
        float mnv = g_pmin[b*NSUB + t];
        float mxv = g_pmax[b*NSUB + t];
        if (t < 24){
            mnv = fminf(mnv, g_pmin[b*NSUB + 32 + t]);
            mxv = fmaxf(mxv, g_pmax[b*NSUB + 32 + t]);
        }
        #pragma unroll
        for (int o = 16; o; o >>= 1){
            mnv = fminf(mnv, __shfl_xor_sync(~0u, mnv, o));
            mxv = fmaxf(mxv, __shfl_xor_sync(~0u, mxv, o));
        }
        if (t == 0){ s_mm[0] = mnv; s_mm[1] = mxv; }
    }
    // zero SAT borders (row 0, col 0 of each 57x57 table); CH*57 = 456 < 768
    if (t < CH*57){
        int cc = t/57, j = t%57;
        sat[cc*CST + j]      = 0.f;     // row 0
        sat[cc*CST + j*57]   = 0.f;     // col 0
    }
    __syncthreads();
    float xmin = s_mm[0];
    float xmax = s_mm[1];
    float inv  = 1.f/(xmax - xmin + 1e-7f);
    const float* xb = x + (size_t)b*HW*CC;

    // load normalized xs into SAT interior (coalesced: 8 consecutive channels per pixel)
    for (int idx = t; idx < HW*CH; idx += TMB){
        int cc = idx & 7; int p = idx >> 3;
        int h = p/56, w = p - h*56;
        float v = (xb[p*CC + c0 + cc] - xmin) * inv;
        sat[cc*CST + (h+1)*57 + (w+1)] = v;
    }
    __syncthreads();

    // row prefix sums (448 rows, one per thread)
    if (t < 448){
        int cc = t/56; int i = (t%56) + 1;
        float* row = sat + cc*CST + i*57;
        float acc = 0.f;
        #pragma unroll
        for (int j = 1; j <= 56; j++){ acc += row[j]; row[j] = acc; }
    }
    __syncthreads();

    // column prefix sums (448 cols, one per thread)
    if (t < 448){
        int cc = t/56; int j = (t%56) + 1;
        float* col = sat + cc*CST + j;
        float acc = 0.f;
        #pragma unroll
        for (int i = 1; i <= 56; i++){ acc += col[i*57]; col[i*57] = acc; }
    }
    __syncthreads();

    // per-thread constants
    float bns = gamma[c] * rsqrtf(bn_var[c] + 1e-3f);
    float bnb = beta[c] - bns*bn_mean[c];
    float bv0 = g_bv[0], bv1 = g_bv[1], bv2 = g_bv[2], bv3 = g_bv[3], bv4 = g_bv[4];
    const float LN2 = 0.69314718055994531f;
    float C1  = LN2 * g_nbv;            // multiplies sqrt(na2)*|alpha|
    const float* S = sat + ci*CST;
    __half2* t12p = ((__half2*)g_t12h) + (size_t)b*HW*CC;

    float asum = 0.f;
    int p0 = t >> 3;                   // 0..95, pixel stride NPG=96 per iter
    const int KK[5] = {2,4,8,16,32};
    const int PB[5] = {0,1,3,7,15};    // TF SAME pad_before = (k-1)/2

    for (int it = 0; it < 33; it++){
        int p = p0 + it*NPG;
        if (p >= HW) break;            // only last iter, warp-granular (p0 >= 64)
        int h = p/56, w = p - h*56;
        float L[5];   // log2(m + eps)  -- MUFU LG2, everything stays in log2 basis
        #pragma unroll
        for (int s = 0; s < 5; s++){
            int r0 = max(h - PB[s], 0), r1 = min(h - PB[s] + KK[s], 56);
            int q0 = max(w - PB[s], 0), q1 = min(w - PB[s] + KK[s], 56);
            float m = S[r1*57 + q1] - S[r0*57 + q1] - S[r1*57 + q0] + S[r0*57 + q0];
            L[s] = __log2f(m + 1e-7f);
        }
        float sumL = (L[0]+L[1]) + (L[2]+L[3]) + L[4];
        // alpha (natural-log OLS slope) == 0.1*(2(L4-L0)+(L3-L1)) in log2 basis
        float alpha = 0.1f * (2.f*(L[4]-L[0]) + (L[3]-L[1]));
        // dot(a,bv) = sum(L*bv) since sum(bv)==0 ;  |a|^2 = sum(L^2) - (sum L)^2/5
        float dotv = L[0]*bv0 + L[1]*bv1 + L[2]*bv2 + L[3]*bv3 + L[4]*bv4;
        float sq   = L[0]*L[0] + L[1]*L[1] + L[2]*L[2] + L[3]*L[3] + L[4]*L[4];
        float na2  = fmaxf(fmaf(-0.2f*sumL, sumL, sq), 0.f);
        float rs   = rsqrtf(na2 + 1e-20f);
        float sqn  = na2 * rs;                              // sqrt(na2), ==0 when na2==0
        float denom = fmaf(sqn * fabsf(alpha), C1, 1e-7f);
        float cosv  = __fdividef(LN2 * alpha * dotv, denom);
        float sim   = fmaf(cosv, 0.5f, 0.5f);
        float sg    = __fdividef(1.f, 1.f + __expf(-fmaf(bns, alpha, bnb)));
        float xs    = (__ldg(&xb[p*CC + c]) - xmin) * inv;  // L2-hit re-read
        t12p[p*CC + c] = __floats2half2_rn(sim * sg, (1.f - sim) * xs);
        asum += alpha;
    }

    // per-channel alpha sum -> squeeze (block owns full H*W of its 8 channels)
    asum += __shfl_xor_sync(~0u, asum, 8);
    asum += __shfl_xor_sync(~0u, asum, 16);
    __shared__ float red[TMB/32][8];
    int lane = t & 31, wp = t >> 5;
    if (lane < 8) red[wp][lane] = asum;
    __syncthreads();
    if (t < 8){
        float s = 0.f;
        #pragma unroll
        for (int i = 0; i < TMB/32; i++) s += red[i][t];
        g_squeeze[b*CC + c0 + t] = s * (1.f/3136.f);
    }
}

// ---------------- kernel C: per-block SE-MLP (smem) + final blend ----------------
__global__ void __launch_bounds__(256) k_final(
    float* __restrict__ out,
    const float* __restrict__ W1, const float* __restrict__ b1,
    const float* __restrict__ W2, const float* __restrict__ b2)
{
    // each block covers 1024 out-float4 = 4096 floats; batch slab = 98 blocks
    int blk = blockIdx.x;
    int b   = blk / 98;
    int t   = threadIdx.x;

    __shared__ float s_sq[CC];
    __shared__ float s_hid[16];
    __shared__ float s_exc[CC];

    if (t < CC) s_sq[t] = g_squeeze[b*CC + t];
    __syncthreads();

    // hidden[j] = relu(b1[j] + sum_c sq[c]*W1[c*16+j]); 256 thr = (j<16) x (cl<16)
    {
        int j = t >> 4, cl = t & 15;
        float acc = 0.f;
        #pragma unroll
        for (int k = 0; k < 8; k++){
            int cc = cl + 16*k;
            acc += s_sq[cc] * __ldg(&W1[cc*16 + j]);
        }
        #pragma unroll
        for (int o = 8; o; o >>= 1) acc += __shfl_xor_sync(~0u, acc, o);
        if (cl == 0) s_hid[j] = fmaxf(acc + __ldg(&b1[j]), 0.f);
    }
    __syncthreads();

    if (t < CC){
        float a = __ldg(&b2[t]);
        #pragma unroll
        for (int j = 0; j < 16; j++) a += s_hid[j] * __ldg(&W2[j*CC + t]);
        s_exc[t] = __fdividef(1.f, 1.f + __expf(-a));
    }
    __syncthreads();

    const float4* exc4 = (const float4*)s_exc;
    #pragma unroll
    for (int it = 0; it < 4; it++){
        int i = blk*1024 + it*256 + t;      // out float4 index (4 channels)
        uint4 u = g_t12h[i];                // 4 x half2(t1,t2)
        float2 p0 = __half22float2(*(__half2*)&u.x);
        float2 p1 = __half22float2(*(__half2*)&u.y);
        float2 p2 = __half22float2(*(__half2*)&u.z);
        float2 p3 = __half22float2(*(__half2*)&u.w);
        float4 e = exc4[i & 31];
        float4 o;
        o.x = fmaf(p0.y, e.x, p0.x);
        o.y = fmaf(p1.y, e.y, p1.x);
        o.z = fmaf(p2.y, e.z, p2.x);
        o.w = fmaf(p3.y, e.w, p3.x);
        ((float4*)out)[i] = o;
    }
}

// ---------------- launch ----------------
extern "C" void kernel_launch(void* const* d_in, const int* in_sizes, int n_in,
                              void* d_out, int out_size)
{
    const float* x       = (const float*)d_in[0];
    const float* kappa   = (const float*)d_in[1];
    const float* W1      = (const float*)d_in[2];
    const float* b1      = (const float*)d_in[3];
    const float* W2      = (const float*)d_in[4];
    const float* b2      = (const float*)d_in[5];
    const float* gamma   = (const float*)d_in[6];
    const float* beta    = (const float*)d_in[7];
    const float* bn_mean = (const float*)d_in[8];
    const float* bn_var  = (const float*)d_in[9];

    cudaFuncSetAttribute(k_main, cudaFuncAttributeMaxDynamicSharedMemorySize, CH*CST*4);

    k_minmax<<<BB*NSUB, 256>>>(x, kappa);
    dim3 gb(CC/CH, BB);
    k_main<<<gb, TMB, CH*CST*4>>>(x, gamma, beta, bn_mean, bn_var);
    k_final<<<NELEM/4096, 256>>>((float*)d_out, W1, b1, W2, b2);
}